// round 2
// baseline (speedup 1.0000x reference)
#include <cuda_runtime.h>

#define NB    15
#define NWIN  64
#define NTOK  144
#define NC    192
#define NH    6
#define NL    32
#define MROWS (NB*NWIN*NTOK)   /* 138240 */
#define BIAS_E 3312

// ---------------- scratch (device globals; no allocs allowed) ----------------
__device__ float g_q[(size_t)NB*NH*NWIN*NTOK*NL];      // 106 MB
__device__ float g_k[(size_t)NB*NH*NWIN*NTOK*NL];      // 106 MB
__device__ float g_v[(size_t)NB*NH*NWIN*NTOK*NL];      // 106 MB
__device__ float g_attn[(size_t)MROWS*NC];             // 106 MB
__device__ float g_bias_t[(size_t)NWIN*NH*BIAS_E];     // 5 MB, layout (w,h,e)

// ---------------- bias table transpose: (e,w,h) -> (w,h,e) -------------------
__global__ __launch_bounds__(256) void bias_transpose_k(const float* __restrict__ bt) {
    int i = blockIdx.x * 256 + threadIdx.x;
    if (i < BIAS_E * NWIN * NH) {
        int e   = i / (NWIN * NH);
        int rem = i - e * (NWIN * NH);
        int w   = rem / NH;
        int h   = rem - w * NH;
        g_bias_t[(w * NH + h) * BIAS_E + e] = bt[i];
    }
}

// ---------------- QKV GEMM: (138240x192) @ (576x192)^T + b, scatter ----------
// Output element (r, j): part=j/192 selects q/k/v; h=(j%192)/32, l=j%32.
// Scatter to per-(b_,h,w) contiguous 144x32 tiles for the attention kernel.
__global__ __launch_bounds__(256) void qkv_gemm_k(
    const float* __restrict__ X, const float* __restrict__ W,
    const float* __restrict__ bias)
{
    __shared__ float As[16][64];
    __shared__ float Bs[16][64];
    const int bm = blockIdx.y * 64;
    const int bn = blockIdx.x * 64;
    const int t  = threadIdx.x;
    const int tx = t & 15, ty = t >> 4;
    const int lr = t >> 2;          // 0..63 tile row
    const int lk = (t & 3) * 4;     // k quad
    float acc[4][4] = {};

    const float* xp = X + (size_t)(bm + lr) * NC + lk;
    const float* wp = W + (size_t)(bn + lr) * NC + lk;

    for (int kt = 0; kt < NC; kt += 16) {
        float4 a = *(const float4*)(xp + kt);
        float4 b = *(const float4*)(wp + kt);
        As[lk+0][lr] = a.x; As[lk+1][lr] = a.y; As[lk+2][lr] = a.z; As[lk+3][lr] = a.w;
        Bs[lk+0][lr] = b.x; Bs[lk+1][lr] = b.y; Bs[lk+2][lr] = b.z; Bs[lk+3][lr] = b.w;
        __syncthreads();
        #pragma unroll
        for (int k = 0; k < 16; k++) {
            float4 av = *(const float4*)&As[k][ty * 4];
            float4 bv = *(const float4*)&Bs[k][tx * 4];
            float am[4] = {av.x, av.y, av.z, av.w};
            float bb[4] = {bv.x, bv.y, bv.z, bv.w};
            #pragma unroll
            for (int i = 0; i < 4; i++)
                #pragma unroll
                for (int j = 0; j < 4; j++)
                    acc[i][j] += am[i] * bb[j];
        }
        __syncthreads();
    }

    #pragma unroll
    for (int i = 0; i < 4; i++) {
        int row  = bm + ty * 4 + i;
        int bidx = row / (NTOK * NWIN);
        int rem  = row - bidx * (NTOK * NWIN);
        int w    = rem / NTOK;
        int n    = rem - w * NTOK;
        #pragma unroll
        for (int j = 0; j < 4; j++) {
            int col  = bn + tx * 4 + j;
            float v  = acc[i][j] + bias[col];
            int part = col / NC;
            int c    = col - part * NC;
            int h    = c >> 5, l = c & 31;
            size_t dst = ((((size_t)(bidx * NH + h) * NWIN + w) * NTOK + n) << 5) + l;
            float* buf = (part == 0) ? g_q : (part == 1) ? g_k : g_v;
            buf[dst] = v;
        }
    }
}

// ---------------- fused attention per (b_, w), loop over 6 heads -------------
// smem: mask(20736) | scores(20736) | q(4608) | k(144x36 pad=5184) | v(4608)
#define SM_FLOATS (20736 + 20736 + 4608 + 5184 + 4608)   /* 55872 -> 223488 B */

__global__ __launch_bounds__(256) void attn_k(const float* __restrict__ mask) {
    extern __shared__ float sm[];
    float* mask_s = sm;
    float* sc     = sm + 20736;
    float* qs     = sm + 41472;
    float* ks     = qs + 4608;
    float* vs     = ks + 5184;

    const int bw = blockIdx.x;          // b_ * 64 + w
    const int t  = threadIdx.x;
    const int b_ = bw / NWIN;
    const int w  = bw - b_ * NWIN;
    const float scale = 0.17677669529663687f;  // 1/sqrt(32)

    const float* mbase = mask + (size_t)bw * (NTOK * NTOK);
    for (int i = t; i < NTOK * NTOK; i += 256) mask_s[i] = mbase[i];

    for (int h = 0; h < NH; h++) {
        __syncthreads();   // protects mask_s (h=0) and q/k/v/sc reuse (h>0)
        size_t off = (((size_t)(b_ * NH + h) * NWIN + w) * NTOK) << 5;
        for (int i = t; i < NTOK * NL; i += 256) {
            int n = i >> 5, l = i & 31;
            qs[i]            = g_q[off + i] * scale;
            ks[n * 36 + l]   = g_k[off + i];
            vs[i]            = g_v[off + i];
        }
        __syncthreads();

        // ---- scores = q*scale @ k^T + bias + mask ----
        const float* bt = g_bias_t + (size_t)(w * NH + h) * BIAS_E;
        for (int idx = t; idx < NTOK * NTOK; idx += 256) {
            int n = idx / NTOK;
            int m = idx - n * NTOK;
            const float4* qp = (const float4*)(qs + n * 32);
            const float4* kp = (const float4*)(ks + m * 36);
            float acc = 0.f;
            #pragma unroll
            for (int q8 = 0; q8 < 8; q8++) {
                float4 a = qp[q8];
                float4 b = kp[q8];
                acc += a.x * b.x + a.y * b.y + a.z * b.z + a.w * b.w;
            }
            // analytic earth-position index
            int zn = n / 72, r1 = n - zn * 72, hn = r1 / 12, wn = r1 - hn * 12;
            int zm = m / 72, r2 = m - zm * 72, hm = r2 / 12, wm = r2 - hm * 12;
            int epi = 828 * (zn + 2 * zm) + 23 * (hn + 6 * hm) + (wn - wm + 11);
            sc[idx] = acc + __ldg(bt + epi) + mask_s[idx];
        }
        __syncthreads();

        // ---- row softmax (warp per row, 8 warps x 18 rows) ----
        {
            int warp = t >> 5, lane = t & 31;
            for (int n = warp; n < NTOK; n += 8) {
                float* row = sc + n * NTOK;
                float mx = -1e30f;
                for (int m = lane; m < NTOK; m += 32) mx = fmaxf(mx, row[m]);
                #pragma unroll
                for (int o = 16; o; o >>= 1) mx = fmaxf(mx, __shfl_xor_sync(0xffffffffu, mx, o));
                float s = 0.f;
                for (int m = lane; m < NTOK; m += 32) {
                    float e = __expf(row[m] - mx);
                    row[m] = e;
                    s += e;
                }
                #pragma unroll
                for (int o = 16; o; o >>= 1) s += __shfl_xor_sync(0xffffffffu, s, o);
                float inv = 1.0f / s;
                for (int m = lane; m < NTOK; m += 32) row[m] *= inv;
            }
        }
        __syncthreads();

        // ---- out = attn @ v  (4 outputs/thread share the attn broadcast) ----
        float* outb = g_attn + ((size_t)bw * NTOK) * NC + h * NL;
        for (int i = t; i < NTOK * 8; i += 256) {
            int n  = i >> 3;
            int lq = i & 7;
            const float*  ar = sc + n * NTOK;
            const float4* vp = (const float4*)(vs + lq * 4);
            float4 a4 = make_float4(0.f, 0.f, 0.f, 0.f);
            #pragma unroll 8
            for (int m = 0; m < NTOK; m++) {
                float a = ar[m];
                float4 vv = vp[m * 8];
                a4.x += a * vv.x; a4.y += a * vv.y; a4.z += a * vv.z; a4.w += a * vv.w;
            }
            *(float4*)(outb + n * NC + lq * 4) = a4;
        }
    }
}

// ---------------- output projection: (138240x192) @ (192x192)^T + b ----------
__global__ __launch_bounds__(256) void proj_gemm_k(
    const float* __restrict__ W, const float* __restrict__ bias,
    float* __restrict__ out)
{
    __shared__ float As[16][64];
    __shared__ float Bs[16][64];
    const int bm = blockIdx.y * 64;
    const int bn = blockIdx.x * 64;
    const int t  = threadIdx.x;
    const int tx = t & 15, ty = t >> 4;
    const int lr = t >> 2;
    const int lk = (t & 3) * 4;
    float acc[4][4] = {};

    const float* xp = g_attn + (size_t)(bm + lr) * NC + lk;
    const float* wp = W + (size_t)(bn + lr) * NC + lk;

    for (int kt = 0; kt < NC; kt += 16) {
        float4 a = *(const float4*)(xp + kt);
        float4 b = *(const float4*)(wp + kt);
        As[lk+0][lr] = a.x; As[lk+1][lr] = a.y; As[lk+2][lr] = a.z; As[lk+3][lr] = a.w;
        Bs[lk+0][lr] = b.x; Bs[lk+1][lr] = b.y; Bs[lk+2][lr] = b.z; Bs[lk+3][lr] = b.w;
        __syncthreads();
        #pragma unroll
        for (int k = 0; k < 16; k++) {
            float4 av = *(const float4*)&As[k][ty * 4];
            float4 bv = *(const float4*)&Bs[k][tx * 4];
            float am[4] = {av.x, av.y, av.z, av.w};
            float bb[4] = {bv.x, bv.y, bv.z, bv.w};
            #pragma unroll
            for (int i = 0; i < 4; i++)
                #pragma unroll
                for (int j = 0; j < 4; j++)
                    acc[i][j] += am[i] * bb[j];
        }
        __syncthreads();
    }

    #pragma unroll
    for (int i = 0; i < 4; i++) {
        int row = bm + ty * 4 + i;
        #pragma unroll
        for (int j = 0; j < 4; j++) {
            int col = bn + tx * 4 + j;
            out[(size_t)row * NC + col] = acc[i][j] + bias[col];
        }
    }
}

// ---------------- launch --------------------------------------------------
extern "C" void kernel_launch(void* const* d_in, const int* in_sizes, int n_in,
                              void* d_out, int out_size)
{
    const float* x          = (const float*)d_in[0];
    const float* mask       = (const float*)d_in[1];
    const float* qkv_w      = (const float*)d_in[2];
    const float* qkv_b      = (const float*)d_in[3];
    const float* proj_w     = (const float*)d_in[4];
    const float* proj_b     = (const float*)d_in[5];
    const float* bias_table = (const float*)d_in[6];
    float* out = (float*)d_out;

    cudaFuncSetAttribute(attn_k, cudaFuncAttributeMaxDynamicSharedMemorySize,
                         SM_FLOATS * sizeof(float));

    bias_transpose_k<<<(BIAS_E * NWIN * NH + 255) / 256, 256>>>(bias_table);
    qkv_gemm_k<<<dim3(9, MROWS / 64), 256>>>(x, qkv_w, qkv_b);
    attn_k<<<NB * NWIN, 256, SM_FLOATS * sizeof(float)>>>(mask);
    proj_gemm_k<<<dim3(3, MROWS / 64), 256>>>(proj_w, proj_b, out);
}

// round 3
// speedup vs baseline: 1.7072x; 1.7072x over previous
#include <cuda_runtime.h>

#define NB    15
#define NWIN  64
#define NTOK  144
#define NC    192
#define NH    6
#define NL    32
#define MROWS (NB*NWIN*NTOK)   /* 138240 */
#define BIAS_E 3312

// ---------------- scratch (device globals; no allocs allowed) ----------------
__device__ float g_q[(size_t)NB*NH*NWIN*NTOK*NL];      // 106 MB
__device__ float g_k[(size_t)NB*NH*NWIN*NTOK*NL];      // 106 MB
__device__ float g_v[(size_t)NB*NH*NWIN*NTOK*NL];      // 106 MB
__device__ float g_attn[(size_t)MROWS*NC];             // 106 MB
__device__ float g_bias_t[(size_t)NWIN*NH*BIAS_E];     // 5 MB, layout (w,h,e)

// ---------------- bias table transpose: (e,w,h) -> (w,h,e) -------------------
__global__ __launch_bounds__(256) void bias_transpose_k(const float* __restrict__ bt) {
    int i = blockIdx.x * 256 + threadIdx.x;
    if (i < BIAS_E * NWIN * NH) {
        int e   = i / (NWIN * NH);
        int rem = i - e * (NWIN * NH);
        int w   = rem / NH;
        int h   = rem - w * NH;
        g_bias_t[(w * NH + h) * BIAS_E + e] = bt[i];
    }
}

// ---------------- QKV GEMM: (138240x192) @ (576x192)^T + b, scatter ----------
__global__ __launch_bounds__(256) void qkv_gemm_k(
    const float* __restrict__ X, const float* __restrict__ W,
    const float* __restrict__ bias)
{
    __shared__ float As[16][64];
    __shared__ float Bs[16][64];
    const int bm = blockIdx.y * 64;
    const int bn = blockIdx.x * 64;
    const int t  = threadIdx.x;
    const int tx = t & 15, ty = t >> 4;
    const int lr = t >> 2;          // 0..63 tile row
    const int lk = (t & 3) * 4;     // k quad
    float acc[4][4] = {};

    const float* xp = X + (size_t)(bm + lr) * NC + lk;
    const float* wp = W + (size_t)(bn + lr) * NC + lk;

    for (int kt = 0; kt < NC; kt += 16) {
        float4 a = *(const float4*)(xp + kt);
        float4 b = *(const float4*)(wp + kt);
        As[lk+0][lr] = a.x; As[lk+1][lr] = a.y; As[lk+2][lr] = a.z; As[lk+3][lr] = a.w;
        Bs[lk+0][lr] = b.x; Bs[lk+1][lr] = b.y; Bs[lk+2][lr] = b.z; Bs[lk+3][lr] = b.w;
        __syncthreads();
        #pragma unroll
        for (int k = 0; k < 16; k++) {
            float4 av = *(const float4*)&As[k][ty * 4];
            float4 bv = *(const float4*)&Bs[k][tx * 4];
            float am[4] = {av.x, av.y, av.z, av.w};
            float bb[4] = {bv.x, bv.y, bv.z, bv.w};
            #pragma unroll
            for (int i = 0; i < 4; i++)
                #pragma unroll
                for (int j = 0; j < 4; j++)
                    acc[i][j] += am[i] * bb[j];
        }
        __syncthreads();
    }

    #pragma unroll
    for (int i = 0; i < 4; i++) {
        int row  = bm + ty * 4 + i;
        int bidx = row / (NTOK * NWIN);
        int rem  = row - bidx * (NTOK * NWIN);
        int w    = rem / NTOK;
        int n    = rem - w * NTOK;
        #pragma unroll
        for (int j = 0; j < 4; j++) {
            int col  = bn + tx * 4 + j;
            float v  = acc[i][j] + bias[col];
            int part = col / NC;
            int c    = col - part * NC;
            int h    = c >> 5, l = c & 31;
            size_t dst = ((((size_t)(bidx * NH + h) * NWIN + w) * NTOK + n) << 5) + l;
            float* buf = (part == 0) ? g_q : (part == 1) ? g_k : g_v;
            buf[dst] = v;
        }
    }
}

// ---------------- flash-style attention: one CTA per (window, head) ----------
// One thread per query row. q + output accumulator in registers, K/V in smem
// read as warp-broadcast, online softmax with rare-rescale branch.
__global__ __launch_bounds__(160) void attn_k(const float* __restrict__ mask) {
    __shared__ float ks[NTOK * NL];      // 18432 B
    __shared__ float vs[NTOK * NL];      // 18432 B
    __shared__ int   epi_off[NTOK];      // 576 B

    const int bx = blockIdx.x;           // bw * 6 + h
    const int h  = bx % NH;
    const int bw = bx / NH;
    const int b_ = bw >> 6;              // NWIN = 64
    const int w  = bw & 63;
    const int t  = threadIdx.x;
    const float scale = 0.17677669529663687f;  // 1/sqrt(32)

    const size_t off = (((size_t)(b_ * NH + h) * NWIN + w) * NTOK) << 5;

    // cooperative K/V tile load (coalesced float4)
    {
        const float4* kg = (const float4*)(g_k + off);
        const float4* vg = (const float4*)(g_v + off);
        float4* ks4 = (float4*)ks;
        float4* vs4 = (float4*)vs;
        for (int i = t; i < NTOK * NL / 4; i += 160) {
            ks4[i] = kg[i];
            vs4[i] = vg[i];
        }
    }
    // epi m-offset: epi(n,m) = base(n) + 1656*zm + 138*hm - wm
    if (t < NTOK) {
        int zm = t / 72, r = t - zm * 72, hm = r / 12, wm = r - hm * 12;
        epi_off[t] = 1656 * zm + 138 * hm - wm;
    }
    __syncthreads();

    if (t < NTOK) {
        // q row into registers (scaled)
        float4 qr[8];
        {
            const float4* qg = (const float4*)(g_q + off + (size_t)t * NL);
            #pragma unroll
            for (int j = 0; j < 8; j++) {
                float4 q4 = qg[j];
                qr[j] = make_float4(q4.x * scale, q4.y * scale, q4.z * scale, q4.w * scale);
            }
        }
        const int zn = t / 72, rn = t - zn * 72, hn = rn / 12, wn = rn - hn * 12;
        const int base_n = 828 * zn + 23 * hn + wn + 11;
        const float* bt   = g_bias_t + (size_t)(w * NH + h) * BIAS_E + base_n;
        const float* mrow = mask + (size_t)bw * (NTOK * NTOK) + (size_t)t * NTOK;

        float mx   = -1e30f;
        float lsum = 0.f;
        float4 o[8];
        #pragma unroll
        for (int j = 0; j < 8; j++) o[j] = make_float4(0.f, 0.f, 0.f, 0.f);

        for (int m = 0; m < NTOK; m++) {
            const float4* kp = (const float4*)(ks + m * NL);
            // dot(q, k[m]) with 4 partial accumulators for ILP
            float s0 = 0.f, s1 = 0.f, s2 = 0.f, s3 = 0.f;
            #pragma unroll
            for (int j = 0; j < 8; j++) {
                float4 k4 = kp[j];
                s0 = fmaf(qr[j].x, k4.x, s0);
                s1 = fmaf(qr[j].y, k4.y, s1);
                s2 = fmaf(qr[j].z, k4.z, s2);
                s3 = fmaf(qr[j].w, k4.w, s3);
            }
            float s = (s0 + s1) + (s2 + s3);
            s += __ldg(bt + epi_off[m]) + __ldg(mrow + m);

            const float4* vp = (const float4*)(vs + m * NL);
            if (s <= mx) {
                float p = __expf(s - mx);
                lsum += p;
                #pragma unroll
                for (int j = 0; j < 8; j++) {
                    float4 v4 = vp[j];
                    o[j].x = fmaf(p, v4.x, o[j].x);
                    o[j].y = fmaf(p, v4.y, o[j].y);
                    o[j].z = fmaf(p, v4.z, o[j].z);
                    o[j].w = fmaf(p, v4.w, o[j].w);
                }
            } else {
                float c = __expf(mx - s);
                mx = s;
                lsum = fmaf(lsum, c, 1.f);
                #pragma unroll
                for (int j = 0; j < 8; j++) {
                    float4 v4 = vp[j];
                    o[j].x = fmaf(o[j].x, c, v4.x);
                    o[j].y = fmaf(o[j].y, c, v4.y);
                    o[j].z = fmaf(o[j].z, c, v4.z);
                    o[j].w = fmaf(o[j].w, c, v4.w);
                }
            }
        }
        const float inv = 1.f / lsum;
        float4* outp = (float4*)(g_attn + ((size_t)bw * NTOK + t) * NC + h * NL);
        #pragma unroll
        for (int j = 0; j < 8; j++) {
            outp[j] = make_float4(o[j].x * inv, o[j].y * inv, o[j].z * inv, o[j].w * inv);
        }
    }
}

// ---------------- output projection: (138240x192) @ (192x192)^T + b ----------
__global__ __launch_bounds__(256) void proj_gemm_k(
    const float* __restrict__ W, const float* __restrict__ bias,
    float* __restrict__ out)
{
    __shared__ float As[16][64];
    __shared__ float Bs[16][64];
    const int bm = blockIdx.y * 64;
    const int bn = blockIdx.x * 64;
    const int t  = threadIdx.x;
    const int tx = t & 15, ty = t >> 4;
    const int lr = t >> 2;
    const int lk = (t & 3) * 4;
    float acc[4][4] = {};

    const float* xp = g_attn + (size_t)(bm + lr) * NC + lk;
    const float* wp = W + (size_t)(bn + lr) * NC + lk;

    for (int kt = 0; kt < NC; kt += 16) {
        float4 a = *(const float4*)(xp + kt);
        float4 b = *(const float4*)(wp + kt);
        As[lk+0][lr] = a.x; As[lk+1][lr] = a.y; As[lk+2][lr] = a.z; As[lk+3][lr] = a.w;
        Bs[lk+0][lr] = b.x; Bs[lk+1][lr] = b.y; Bs[lk+2][lr] = b.z; Bs[lk+3][lr] = b.w;
        __syncthreads();
        #pragma unroll
        for (int k = 0; k < 16; k++) {
            float4 av = *(const float4*)&As[k][ty * 4];
            float4 bv = *(const float4*)&Bs[k][tx * 4];
            float am[4] = {av.x, av.y, av.z, av.w};
            float bb[4] = {bv.x, bv.y, bv.z, bv.w};
            #pragma unroll
            for (int i = 0; i < 4; i++)
                #pragma unroll
                for (int j = 0; j < 4; j++)
                    acc[i][j] += am[i] * bb[j];
        }
        __syncthreads();
    }

    #pragma unroll
    for (int i = 0; i < 4; i++) {
        int row = bm + ty * 4 + i;
        #pragma unroll
        for (int j = 0; j < 4; j++) {
            int col = bn + tx * 4 + j;
            out[(size_t)row * NC + col] = acc[i][j] + bias[col];
        }
    }
}

// ---------------- launch --------------------------------------------------
extern "C" void kernel_launch(void* const* d_in, const int* in_sizes, int n_in,
                              void* d_out, int out_size)
{
    const float* x          = (const float*)d_in[0];
    const float* mask       = (const float*)d_in[1];
    const float* qkv_w      = (const float*)d_in[2];
    const float* qkv_b      = (const float*)d_in[3];
    const float* proj_w     = (const float*)d_in[4];
    const float* proj_b     = (const float*)d_in[5];
    const float* bias_table = (const float*)d_in[6];
    float* out = (float*)d_out;

    bias_transpose_k<<<(BIAS_E * NWIN * NH + 255) / 256, 256>>>(bias_table);
    qkv_gemm_k<<<dim3(9, MROWS / 64), 256>>>(x, qkv_w, qkv_b);
    attn_k<<<NB * NWIN * NH, 160>>>(mask);
    proj_gemm_k<<<dim3(3, MROWS / 64), 256>>>(proj_w, proj_b, out);
}

// round 4
// speedup vs baseline: 2.7278x; 1.5978x over previous
#include <cuda_runtime.h>
#include <cstdint>

#define NB    15
#define NWIN  64
#define NTOK  144
#define NC    192
#define NH    6
#define NL    32
#define MROWS (NB*NWIN*NTOK)   /* 138240 */
#define BIAS_E 3312

// ---------------- scratch (device globals; no allocs allowed) ----------------
__device__ float g_q[(size_t)NB*NH*NWIN*NTOK*NL];      // 106 MB
__device__ float g_k[(size_t)NB*NH*NWIN*NTOK*NL];      // 106 MB
__device__ float g_v[(size_t)NB*NH*NWIN*NTOK*NL];      // 106 MB
__device__ float g_attn[(size_t)MROWS*NC];             // 106 MB
__device__ float g_bias_t[(size_t)NWIN*NH*BIAS_E];     // 5 MB, layout (w,h,e)

__device__ __forceinline__ uint32_t f2tf32(float x) {
    uint32_t r;
    asm("cvt.rna.tf32.f32 %0, %1;" : "=r"(r) : "f"(x));
    return r;
}

__device__ __forceinline__ void mma_tf32(float c[4], uint32_t a0, uint32_t a1,
                                         uint32_t a2, uint32_t a3,
                                         uint32_t b0, uint32_t b1) {
    asm volatile(
        "mma.sync.aligned.m16n8k8.row.col.f32.tf32.tf32.f32 "
        "{%0,%1,%2,%3}, {%4,%5,%6,%7}, {%8,%9}, {%0,%1,%2,%3};"
        : "+f"(c[0]), "+f"(c[1]), "+f"(c[2]), "+f"(c[3])
        : "r"(a0), "r"(a1), "r"(a2), "r"(a3), "r"(b0), "r"(b1));
}

// ---------------- bias table transpose: (e,w,h) -> (w,h,e) -------------------
__global__ __launch_bounds__(256) void bias_transpose_k(const float* __restrict__ bt) {
    int i = blockIdx.x * 256 + threadIdx.x;
    if (i < BIAS_E * NWIN * NH) {
        int e   = i / (NWIN * NH);
        int rem = i - e * (NWIN * NH);
        int w   = rem / NH;
        int h   = rem - w * NH;
        g_bias_t[(w * NH + h) * BIAS_E + e] = bt[i];
    }
}

// ====================== tf32 tensor-core GEMM (128x64 tile) ===================
// X:(M x 192) row-major, W:(Ntot x 192) row-major; C = X @ W^T (+bias in epi).
// Fragment smem layouts padded to 36 floats/row -> conflict-free LDS/STS.

#define KPAD 36

struct FragC { float c[2][4][4]; };  // [fm][fn][4]

__device__ __forceinline__ void gemm_tile_tf32(
    const float* __restrict__ X, const float* __restrict__ W,
    int bm, int bn, FragC& fc,
    float (*As)[KPAD], float (*Bs)[KPAD])
{
    const int t    = threadIdx.x;
    const int lane = t & 31;
    const int warp = t >> 5;
    const int wm   = warp & 3;          // 0..3  (M)
    const int wn   = warp >> 2;         // 0..1  (N)
    const int g    = lane >> 2;         // 0..7
    const int tg   = lane & 3;          // 0..3

    #pragma unroll
    for (int fm = 0; fm < 2; fm++)
        #pragma unroll
        for (int fn = 0; fn < 4; fn++)
            #pragma unroll
            for (int i = 0; i < 4; i++) fc.c[fm][fn][i] = 0.f;

    // global load indices
    const int arow = t >> 1;                 // 0..127
    const int acol = (t & 1) * 16;           // 0 or 16
    const int brow = t >> 2;                 // 0..63
    const int bcol = (t & 3) * 8;            // 0,8,16,24

    for (int kc = 0; kc < NC; kc += 32) {
        // ---- fill smem (cvt to tf32 at store) ----
        {
            const float4* ap = (const float4*)(X + (size_t)(bm + arow) * NC + kc + acol);
            #pragma unroll
            for (int i = 0; i < 4; i++) {
                float4 a = ap[i];
                uint32_t* d = (uint32_t*)&As[arow][acol + i * 4];
                d[0] = f2tf32(a.x); d[1] = f2tf32(a.y);
                d[2] = f2tf32(a.z); d[3] = f2tf32(a.w);
            }
            const float4* bp = (const float4*)(W + (size_t)(bn + brow) * NC + kc + bcol);
            #pragma unroll
            for (int i = 0; i < 2; i++) {
                float4 b = bp[i];
                uint32_t* d = (uint32_t*)&Bs[brow][bcol + i * 4];
                d[0] = f2tf32(b.x); d[1] = f2tf32(b.y);
                d[2] = f2tf32(b.z); d[3] = f2tf32(b.w);
            }
        }
        __syncthreads();

        #pragma unroll
        for (int kk = 0; kk < 4; kk++) {
            const int kb = kk * 8;
            uint32_t a[2][4], b[4][2];
            #pragma unroll
            for (int fm = 0; fm < 2; fm++) {
                const int r = wm * 32 + fm * 16 + g;
                const uint32_t* A0 = (const uint32_t*)As[r];
                const uint32_t* A8 = (const uint32_t*)As[r + 8];
                a[fm][0] = A0[kb + tg];
                a[fm][1] = A8[kb + tg];
                a[fm][2] = A0[kb + tg + 4];
                a[fm][3] = A8[kb + tg + 4];
            }
            #pragma unroll
            for (int fn = 0; fn < 4; fn++) {
                const uint32_t* B0 = (const uint32_t*)Bs[wn * 32 + fn * 8 + g];
                b[fn][0] = B0[kb + tg];
                b[fn][1] = B0[kb + tg + 4];
            }
            #pragma unroll
            for (int fm = 0; fm < 2; fm++)
                #pragma unroll
                for (int fn = 0; fn < 4; fn++)
                    mma_tf32(fc.c[fm][fn], a[fm][0], a[fm][1], a[fm][2], a[fm][3],
                             b[fn][0], b[fn][1]);
        }
        __syncthreads();
    }
}

// ---------------- QKV GEMM + scatter epilogue --------------------------------
__global__ __launch_bounds__(256) void qkv_gemm_k(
    const float* __restrict__ X, const float* __restrict__ W,
    const float* __restrict__ bias)
{
    __shared__ float As[128][KPAD];
    __shared__ float Bs[64][KPAD];
    const int bm = blockIdx.y * 128;
    const int bn = blockIdx.x * 64;

    FragC fc;
    gemm_tile_tf32(X, W, bm, bn, fc, As, Bs);

    const int lane = threadIdx.x & 31;
    const int warp = threadIdx.x >> 5;
    const int wm = warp & 3, wn = warp >> 2;
    const int g = lane >> 2, tg = lane & 3;

    #pragma unroll
    for (int fm = 0; fm < 2; fm++) {
        #pragma unroll
        for (int i = 0; i < 2; i++) {       // row halves (+0, +8)
            const int row  = bm + wm * 32 + fm * 16 + g + i * 8;
            const int bidx = row / (NTOK * NWIN);
            const int rem  = row - bidx * (NTOK * NWIN);
            const int w    = rem / NTOK;
            const int n    = rem - w * NTOK;
            #pragma unroll
            for (int fn = 0; fn < 4; fn++) {
                const int col  = bn + wn * 32 + fn * 8 + 2 * tg;   // even, l<=30
                const int part = col / NC;
                const int c    = col - part * NC;
                const int h    = c >> 5, l = c & 31;
                float* buf = (part == 0) ? g_q : (part == 1) ? g_k : g_v;
                size_t dst = ((((size_t)(bidx * NH + h) * NWIN + w) * NTOK + n) << 5) + l;
                float2 v2 = make_float2(fc.c[fm][fn][2 * i]     + bias[col],
                                        fc.c[fm][fn][2 * i + 1] + bias[col + 1]);
                *(float2*)(buf + dst) = v2;
            }
        }
    }
}

// ---------------- projection GEMM ---------------------------------------------
__global__ __launch_bounds__(256) void proj_gemm_k(
    const float* __restrict__ W, const float* __restrict__ bias,
    float* __restrict__ out)
{
    __shared__ float As[128][KPAD];
    __shared__ float Bs[64][KPAD];
    const int bm = blockIdx.y * 128;
    const int bn = blockIdx.x * 64;

    FragC fc;
    gemm_tile_tf32(g_attn, W, bm, bn, fc, As, Bs);

    const int lane = threadIdx.x & 31;
    const int warp = threadIdx.x >> 5;
    const int wm = warp & 3, wn = warp >> 2;
    const int g = lane >> 2, tg = lane & 3;

    #pragma unroll
    for (int fm = 0; fm < 2; fm++) {
        #pragma unroll
        for (int i = 0; i < 2; i++) {
            const int row = bm + wm * 32 + fm * 16 + g + i * 8;
            #pragma unroll
            for (int fn = 0; fn < 4; fn++) {
                const int col = bn + wn * 32 + fn * 8 + 2 * tg;
                float2 v2 = make_float2(fc.c[fm][fn][2 * i]     + bias[col],
                                        fc.c[fm][fn][2 * i + 1] + bias[col + 1]);
                *(float2*)(out + (size_t)row * NC + col) = v2;
            }
        }
    }
}

// ---------------- flash-style attention: one CTA per (window, head) ----------
__global__ __launch_bounds__(160) void attn_k(const float* __restrict__ mask) {
    __shared__ float ks[NTOK * NL];
    __shared__ float vs[NTOK * NL];
    __shared__ int   epi_off[NTOK];

    const int bx = blockIdx.x;           // bw * 6 + h
    const int h  = bx % NH;
    const int bw = bx / NH;
    const int b_ = bw >> 6;
    const int w  = bw & 63;
    const int t  = threadIdx.x;
    const float scale = 0.17677669529663687f;

    const size_t off = (((size_t)(b_ * NH + h) * NWIN + w) * NTOK) << 5;

    {
        const float4* kg = (const float4*)(g_k + off);
        const float4* vg = (const float4*)(g_v + off);
        float4* ks4 = (float4*)ks;
        float4* vs4 = (float4*)vs;
        for (int i = t; i < NTOK * NL / 4; i += 160) {
            ks4[i] = kg[i];
            vs4[i] = vg[i];
        }
    }
    if (t < NTOK) {
        int zm = t / 72, r = t - zm * 72, hm = r / 12, wm = r - hm * 12;
        epi_off[t] = 1656 * zm + 138 * hm - wm;
    }
    __syncthreads();

    if (t < NTOK) {
        float4 qr[8];
        {
            const float4* qg = (const float4*)(g_q + off + (size_t)t * NL);
            #pragma unroll
            for (int j = 0; j < 8; j++) {
                float4 q4 = qg[j];
                qr[j] = make_float4(q4.x * scale, q4.y * scale, q4.z * scale, q4.w * scale);
            }
        }
        const int zn = t / 72, rn = t - zn * 72, hn = rn / 12, wn = rn - hn * 12;
        const int base_n = 828 * zn + 23 * hn + wn + 11;
        const float* bt   = g_bias_t + (size_t)(w * NH + h) * BIAS_E + base_n;
        const float* mrow = mask + (size_t)bw * (NTOK * NTOK) + (size_t)t * NTOK;

        float mx   = -1e30f;
        float lsum = 0.f;
        float4 o[8];
        #pragma unroll
        for (int j = 0; j < 8; j++) o[j] = make_float4(0.f, 0.f, 0.f, 0.f);

        for (int m = 0; m < NTOK; m++) {
            const float4* kp = (const float4*)(ks + m * NL);
            float s0 = 0.f, s1 = 0.f, s2 = 0.f, s3 = 0.f;
            #pragma unroll
            for (int j = 0; j < 8; j++) {
                float4 k4 = kp[j];
                s0 = fmaf(qr[j].x, k4.x, s0);
                s1 = fmaf(qr[j].y, k4.y, s1);
                s2 = fmaf(qr[j].z, k4.z, s2);
                s3 = fmaf(qr[j].w, k4.w, s3);
            }
            float s = (s0 + s1) + (s2 + s3);
            s += __ldg(bt + epi_off[m]) + __ldg(mrow + m);

            const float4* vp = (const float4*)(vs + m * NL);
            if (s <= mx) {
                float p = __expf(s - mx);
                lsum += p;
                #pragma unroll
                for (int j = 0; j < 8; j++) {
                    float4 v4 = vp[j];
                    o[j].x = fmaf(p, v4.x, o[j].x);
                    o[j].y = fmaf(p, v4.y, o[j].y);
                    o[j].z = fmaf(p, v4.z, o[j].z);
                    o[j].w = fmaf(p, v4.w, o[j].w);
                }
            } else {
                float c = __expf(mx - s);
                mx = s;
                lsum = fmaf(lsum, c, 1.f);
                #pragma unroll
                for (int j = 0; j < 8; j++) {
                    float4 v4 = vp[j];
                    o[j].x = fmaf(o[j].x, c, v4.x);
                    o[j].y = fmaf(o[j].y, c, v4.y);
                    o[j].z = fmaf(o[j].z, c, v4.z);
                    o[j].w = fmaf(o[j].w, c, v4.w);
                }
            }
        }
        const float inv = 1.f / lsum;
        float4* outp = (float4*)(g_attn + ((size_t)bw * NTOK + t) * NC + h * NL);
        #pragma unroll
        for (int j = 0; j < 8; j++) {
            outp[j] = make_float4(o[j].x * inv, o[j].y * inv, o[j].z * inv, o[j].w * inv);
        }
    }
}

// ---------------- launch --------------------------------------------------
extern "C" void kernel_launch(void* const* d_in, const int* in_sizes, int n_in,
                              void* d_out, int out_size)
{
    const float* x          = (const float*)d_in[0];
    const float* mask       = (const float*)d_in[1];
    const float* qkv_w      = (const float*)d_in[2];
    const float* qkv_b      = (const float*)d_in[3];
    const float* proj_w     = (const float*)d_in[4];
    const float* proj_b     = (const float*)d_in[5];
    const float* bias_table = (const float*)d_in[6];
    float* out = (float*)d_out;

    bias_transpose_k<<<(BIAS_E * NWIN * NH + 255) / 256, 256>>>(bias_table);
    qkv_gemm_k<<<dim3(9, MROWS / 128), 256>>>(x, qkv_w, qkv_b);
    attn_k<<<NB * NWIN * NH, 160>>>(mask);
    proj_gemm_k<<<dim3(3, MROWS / 128), 256>>>(proj_w, proj_b, out);
}

// round 5
// speedup vs baseline: 2.7289x; 1.0004x over previous
#include <cuda_runtime.h>
#include <cstdint>

#define NB    15
#define NWIN  64
#define NTOK  144
#define NC    192
#define NH    6
#define NL    32
#define MROWS (NB*NWIN*NTOK)   /* 138240 */
#define BIAS_E 3312

typedef unsigned long long ull;

// ---------------- scratch (device globals; no allocs allowed) ----------------
__device__ float g_q[(size_t)NB*NH*NWIN*NTOK*NL];      // 106 MB (pre-scaled)
__device__ float g_k[(size_t)NB*NH*NWIN*NTOK*NL];      // 106 MB
__device__ float g_v[(size_t)NB*NH*NWIN*NTOK*NL];      // 106 MB
__device__ float g_attn[(size_t)MROWS*NC];             // 106 MB
__device__ float g_bias_t[(size_t)NWIN*NH*BIAS_E];     // 5 MB, layout (w,h,e)

__device__ __forceinline__ uint32_t f2tf32(float x) {
    uint32_t r;
    asm("cvt.rna.tf32.f32 %0, %1;" : "=r"(r) : "f"(x));
    return r;
}

__device__ __forceinline__ void mma_tf32(float c[4], uint32_t a0, uint32_t a1,
                                         uint32_t a2, uint32_t a3,
                                         uint32_t b0, uint32_t b1) {
    asm volatile(
        "mma.sync.aligned.m16n8k8.row.col.f32.tf32.tf32.f32 "
        "{%0,%1,%2,%3}, {%4,%5,%6,%7}, {%8,%9}, {%0,%1,%2,%3};"
        : "+f"(c[0]), "+f"(c[1]), "+f"(c[2]), "+f"(c[3])
        : "r"(a0), "r"(a1), "r"(a2), "r"(a3), "r"(b0), "r"(b1));
}

// ---- packed fp32x2 helpers (sm_103a FFMA2 path, PTX-only) ----
__device__ __forceinline__ ull fma2(ull a, ull b, ull c) {
    ull d;
    asm("fma.rn.f32x2 %0, %1, %2, %3;" : "=l"(d) : "l"(a), "l"(b), "l"(c));
    return d;
}
__device__ __forceinline__ ull mul2(ull a, ull b) {
    ull d;
    asm("mul.rn.f32x2 %0, %1, %2;" : "=l"(d) : "l"(a), "l"(b));
    return d;
}
__device__ __forceinline__ ull pack2(float x, float y) {
    ull d;
    asm("mov.b64 %0, {%1,%2};" : "=l"(d) : "f"(x), "f"(y));
    return d;
}
union F4U { float4 f; struct { ull lo, hi; } u; };

// ---------------- bias table transpose: (e,w,h) -> (w,h,e) -------------------
__global__ __launch_bounds__(256) void bias_transpose_k(const float* __restrict__ bt) {
    int i = blockIdx.x * 256 + threadIdx.x;
    if (i < BIAS_E * NWIN * NH) {
        int e   = i / (NWIN * NH);
        int rem = i - e * (NWIN * NH);
        int w   = rem / NH;
        int h   = rem - w * NH;
        g_bias_t[(w * NH + h) * BIAS_E + e] = bt[i];
    }
}

// ====================== tf32 tensor-core GEMM (128x64 tile) ===================
#define KPAD 36

struct FragC { float c[2][4][4]; };  // [fm][fn][4]

__device__ __forceinline__ void gemm_tile_tf32(
    const float* __restrict__ X, const float* __restrict__ W,
    int bm, int bn, FragC& fc,
    float (*As)[KPAD], float (*Bs)[KPAD])
{
    const int t    = threadIdx.x;
    const int lane = t & 31;
    const int warp = t >> 5;
    const int wm   = warp & 3;
    const int wn   = warp >> 2;
    const int g    = lane >> 2;
    const int tg   = lane & 3;

    #pragma unroll
    for (int fm = 0; fm < 2; fm++)
        #pragma unroll
        for (int fn = 0; fn < 4; fn++)
            #pragma unroll
            for (int i = 0; i < 4; i++) fc.c[fm][fn][i] = 0.f;

    const int arow = t >> 1;
    const int acol = (t & 1) * 16;
    const int brow = t >> 2;
    const int bcol = (t & 3) * 8;

    const float* Xb = X + (size_t)(bm + arow) * NC + acol;
    const float* Wb = W + (size_t)(bn + brow) * NC + bcol;

    float4 pa[4], pb[2];
    #pragma unroll
    for (int i = 0; i < 4; i++) pa[i] = *(const float4*)(Xb + i * 4);
    #pragma unroll
    for (int i = 0; i < 2; i++) pb[i] = *(const float4*)(Wb + i * 4);

    for (int kc = 0; kc < NC; kc += 32) {
        // ---- store prefetched chunk to smem (cvt to tf32 at store) ----
        #pragma unroll
        for (int i = 0; i < 4; i++) {
            uint32_t* d = (uint32_t*)&As[arow][acol + i * 4];
            d[0] = f2tf32(pa[i].x); d[1] = f2tf32(pa[i].y);
            d[2] = f2tf32(pa[i].z); d[3] = f2tf32(pa[i].w);
        }
        #pragma unroll
        for (int i = 0; i < 2; i++) {
            uint32_t* d = (uint32_t*)&Bs[brow][bcol + i * 4];
            d[0] = f2tf32(pb[i].x); d[1] = f2tf32(pb[i].y);
            d[2] = f2tf32(pb[i].z); d[3] = f2tf32(pb[i].w);
        }
        __syncthreads();

        // ---- prefetch next chunk (latency hidden behind MMAs) ----
        if (kc + 32 < NC) {
            #pragma unroll
            for (int i = 0; i < 4; i++) pa[i] = *(const float4*)(Xb + kc + 32 + i * 4);
            #pragma unroll
            for (int i = 0; i < 2; i++) pb[i] = *(const float4*)(Wb + kc + 32 + i * 4);
        }

        #pragma unroll
        for (int kk = 0; kk < 4; kk++) {
            const int kb = kk * 8;
            uint32_t a[2][4], b[4][2];
            #pragma unroll
            for (int fm = 0; fm < 2; fm++) {
                const int r = wm * 32 + fm * 16 + g;
                const uint32_t* A0 = (const uint32_t*)As[r];
                const uint32_t* A8 = (const uint32_t*)As[r + 8];
                a[fm][0] = A0[kb + tg];
                a[fm][1] = A8[kb + tg];
                a[fm][2] = A0[kb + tg + 4];
                a[fm][3] = A8[kb + tg + 4];
            }
            #pragma unroll
            for (int fn = 0; fn < 4; fn++) {
                const uint32_t* B0 = (const uint32_t*)Bs[wn * 32 + fn * 8 + g];
                b[fn][0] = B0[kb + tg];
                b[fn][1] = B0[kb + tg + 4];
            }
            #pragma unroll
            for (int fm = 0; fm < 2; fm++)
                #pragma unroll
                for (int fn = 0; fn < 4; fn++)
                    mma_tf32(fc.c[fm][fn], a[fm][0], a[fm][1], a[fm][2], a[fm][3],
                             b[fn][0], b[fn][1]);
        }
        __syncthreads();
    }
}

// ---------------- QKV GEMM + scatter epilogue (q pre-scaled) -----------------
__global__ __launch_bounds__(256) void qkv_gemm_k(
    const float* __restrict__ X, const float* __restrict__ W,
    const float* __restrict__ bias)
{
    __shared__ float As[128][KPAD];
    __shared__ float Bs[64][KPAD];
    const int bm = blockIdx.y * 128;
    const int bn = blockIdx.x * 64;

    FragC fc;
    gemm_tile_tf32(X, W, bm, bn, fc, As, Bs);

    const int lane = threadIdx.x & 31;
    const int warp = threadIdx.x >> 5;
    const int wm = warp & 3, wn = warp >> 2;
    const int g = lane >> 2, tg = lane & 3;
    const float scale = 0.17677669529663687f;  // 1/sqrt(32)

    #pragma unroll
    for (int fm = 0; fm < 2; fm++) {
        #pragma unroll
        for (int i = 0; i < 2; i++) {
            const int row  = bm + wm * 32 + fm * 16 + g + i * 8;
            const int bidx = row / (NTOK * NWIN);
            const int rem  = row - bidx * (NTOK * NWIN);
            const int w    = rem / NTOK;
            const int n    = rem - w * NTOK;
            #pragma unroll
            for (int fn = 0; fn < 4; fn++) {
                const int col  = bn + wn * 32 + fn * 8 + 2 * tg;
                const int part = col / NC;
                const int c    = col - part * NC;
                const int h    = c >> 5, l = c & 31;
                float* buf = (part == 0) ? g_q : (part == 1) ? g_k : g_v;
                size_t dst = ((((size_t)(bidx * NH + h) * NWIN + w) * NTOK + n) << 5) + l;
                float2 v2 = make_float2(fc.c[fm][fn][2 * i]     + bias[col],
                                        fc.c[fm][fn][2 * i + 1] + bias[col + 1]);
                if (part == 0) { v2.x *= scale; v2.y *= scale; }
                *(float2*)(buf + dst) = v2;
            }
        }
    }
}

// ---------------- projection GEMM --------------------------------------------
__global__ __launch_bounds__(256) void proj_gemm_k(
    const float* __restrict__ W, const float* __restrict__ bias,
    float* __restrict__ out)
{
    __shared__ float As[128][KPAD];
    __shared__ float Bs[64][KPAD];
    const int bm = blockIdx.y * 128;
    const int bn = blockIdx.x * 64;

    FragC fc;
    gemm_tile_tf32(g_attn, W, bm, bn, fc, As, Bs);

    const int lane = threadIdx.x & 31;
    const int warp = threadIdx.x >> 5;
    const int wm = warp & 3, wn = warp >> 2;
    const int g = lane >> 2, tg = lane & 3;

    #pragma unroll
    for (int fm = 0; fm < 2; fm++) {
        #pragma unroll
        for (int i = 0; i < 2; i++) {
            const int row = bm + wm * 32 + fm * 16 + g + i * 8;
            #pragma unroll
            for (int fn = 0; fn < 4; fn++) {
                const int col = bn + wn * 32 + fn * 8 + 2 * tg;
                float2 v2 = make_float2(fc.c[fm][fn][2 * i]     + bias[col],
                                        fc.c[fm][fn][2 * i + 1] + bias[col + 1]);
                *(float2*)(out + (size_t)row * NC + col) = v2;
            }
        }
    }
}

// ---------------- flash-style attention, f32x2 packed math -------------------
__global__ __launch_bounds__(160) void attn_k(const float* __restrict__ mask) {
    __shared__ float ks[NTOK * NL];
    __shared__ float vs[NTOK * NL];
    __shared__ int   epi_off[NTOK];

    const int bx = blockIdx.x;           // bw * 6 + h
    const int h  = bx % NH;
    const int bw = bx / NH;
    const int b_ = bw >> 6;
    const int w  = bw & 63;
    const int t  = threadIdx.x;

    const size_t off = (((size_t)(b_ * NH + h) * NWIN + w) * NTOK) << 5;

    {
        const float4* kg = (const float4*)(g_k + off);
        const float4* vg = (const float4*)(g_v + off);
        float4* ks4 = (float4*)ks;
        float4* vs4 = (float4*)vs;
        for (int i = t; i < NTOK * NL / 4; i += 160) {
            ks4[i] = kg[i];
            vs4[i] = vg[i];
        }
    }
    if (t < NTOK) {
        int zm = t / 72, r = t - zm * 72, hm = r / 12, wm = r - hm * 12;
        epi_off[t] = 1656 * zm + 138 * hm - wm;
    }
    __syncthreads();

    if (t < NTOK) {
        // q row (pre-scaled) into packed register pairs
        ull qr[16];
        {
            const float4* qg = (const float4*)(g_q + off + (size_t)t * NL);
            #pragma unroll
            for (int j = 0; j < 8; j++) {
                F4U q4; q4.f = qg[j];
                qr[2 * j]     = q4.u.lo;
                qr[2 * j + 1] = q4.u.hi;
            }
        }
        const int zn = t / 72, rn = t - zn * 72, hn = rn / 12, wn = rn - hn * 12;
        const int base_n = 828 * zn + 23 * hn + wn + 11;
        const float* bt   = g_bias_t + (size_t)(w * NH + h) * BIAS_E + base_n;
        const float* mrow = mask + (size_t)bw * (NTOK * NTOK) + (size_t)t * NTOK;

        float mx   = -1e30f;
        float lsum = 0.f;
        ull o[16];
        #pragma unroll
        for (int j = 0; j < 16; j++) o[j] = 0ull;   // (0.f, 0.f)

        for (int m = 0; m < NTOK; m++) {
            const float4* kp4 = (const float4*)(ks + m * NL);
            ull a0 = 0ull, a1 = 0ull, a2 = 0ull, a3 = 0ull;
            #pragma unroll
            for (int j = 0; j < 4; j++) {
                F4U k4; k4.f = kp4[2 * j];
                F4U k5; k5.f = kp4[2 * j + 1];
                a0 = fma2(qr[4 * j],     k4.u.lo, a0);
                a1 = fma2(qr[4 * j + 1], k4.u.hi, a1);
                a2 = fma2(qr[4 * j + 2], k5.u.lo, a2);
                a3 = fma2(qr[4 * j + 3], k5.u.hi, a3);
            }
            float2 f0 = *(float2*)&a0, f1 = *(float2*)&a1;
            float2 f2 = *(float2*)&a2, f3 = *(float2*)&a3;
            float s = ((f0.x + f0.y) + (f1.x + f1.y)) + ((f2.x + f2.y) + (f3.x + f3.y));
            s += __ldg(bt + epi_off[m]) + __ldg(mrow + m);

            const float4* vp4 = (const float4*)(vs + m * NL);
            if (s <= mx) {
                float p = __expf(s - mx);
                lsum += p;
                ull pp = pack2(p, p);
                #pragma unroll
                for (int j = 0; j < 8; j++) {
                    F4U v4; v4.f = vp4[j];
                    o[2 * j]     = fma2(pp, v4.u.lo, o[2 * j]);
                    o[2 * j + 1] = fma2(pp, v4.u.hi, o[2 * j + 1]);
                }
            } else {
                float c = __expf(mx - s);
                mx = s;
                lsum = fmaf(lsum, c, 1.f);
                ull cc = pack2(c, c);
                #pragma unroll
                for (int j = 0; j < 8; j++) {
                    F4U v4; v4.f = vp4[j];
                    o[2 * j]     = fma2(o[2 * j],     cc, v4.u.lo);
                    o[2 * j + 1] = fma2(o[2 * j + 1], cc, v4.u.hi);
                }
            }
        }
        const float inv = 1.f / lsum;
        const ull ii = pack2(inv, inv);
        float4* outp = (float4*)(g_attn + ((size_t)bw * NTOK + t) * NC + h * NL);
        #pragma unroll
        for (int j = 0; j < 8; j++) {
            F4U r;
            r.u.lo = mul2(o[2 * j], ii);
            r.u.hi = mul2(o[2 * j + 1], ii);
            outp[j] = r.f;
        }
    }
}

// ---------------- launch --------------------------------------------------
extern "C" void kernel_launch(void* const* d_in, const int* in_sizes, int n_in,
                              void* d_out, int out_size)
{
    const float* x          = (const float*)d_in[0];
    const float* mask       = (const float*)d_in[1];
    const float* qkv_w      = (const float*)d_in[2];
    const float* qkv_b      = (const float*)d_in[3];
    const float* proj_w     = (const float*)d_in[4];
    const float* proj_b     = (const float*)d_in[5];
    const float* bias_table = (const float*)d_in[6];
    float* out = (float*)d_out;

    bias_transpose_k<<<(BIAS_E * NWIN * NH + 255) / 256, 256>>>(bias_table);
    qkv_gemm_k<<<dim3(9, MROWS / 128), 256>>>(x, qkv_w, qkv_b);
    attn_k<<<NB * NWIN * NH, 160>>>(mask);
    proj_gemm_k<<<dim3(3, MROWS / 128), 256>>>(proj_w, proj_b, out);
}

// round 6
// speedup vs baseline: 3.1230x; 1.1444x over previous
#include <cuda_runtime.h>
#include <cstdint>

#define NB    15
#define NWIN  64
#define NTOK  144
#define NC    192
#define NH    6
#define NL    32
#define MROWS (NB*NWIN*NTOK)   /* 138240 */
#define BIAS_E 3312

// ---------------- scratch (device globals; no allocs allowed) ----------------
__device__ float g_q[(size_t)NB*NH*NWIN*NTOK*NL];      // 106 MB (pre-scaled)
__device__ float g_k[(size_t)NB*NH*NWIN*NTOK*NL];      // 106 MB
__device__ float g_v[(size_t)NB*NH*NWIN*NTOK*NL];      // 106 MB
__device__ float g_attn[(size_t)MROWS*NC];             // 106 MB
__device__ float g_bias_t[(size_t)NWIN*NH*BIAS_E];     // 5 MB, layout (w,h,e)

__device__ __forceinline__ uint32_t f2tf32(float x) {
    uint32_t r;
    asm("cvt.rna.tf32.f32 %0, %1;" : "=r"(r) : "f"(x));
    return r;
}

__device__ __forceinline__ void mma_tf32(float c[4], uint32_t a0, uint32_t a1,
                                         uint32_t a2, uint32_t a3,
                                         uint32_t b0, uint32_t b1) {
    asm volatile(
        "mma.sync.aligned.m16n8k8.row.col.f32.tf32.tf32.f32 "
        "{%0,%1,%2,%3}, {%4,%5,%6,%7}, {%8,%9}, {%0,%1,%2,%3};"
        : "+f"(c[0]), "+f"(c[1]), "+f"(c[2]), "+f"(c[3])
        : "r"(a0), "r"(a1), "r"(a2), "r"(a3), "r"(b0), "r"(b1));
}

// ---------------- bias table transpose: (e,w,h) -> (w,h,e) -------------------
__global__ __launch_bounds__(256) void bias_transpose_k(const float* __restrict__ bt) {
    int i = blockIdx.x * 256 + threadIdx.x;
    if (i < BIAS_E * NWIN * NH) {
        int e   = i / (NWIN * NH);
        int rem = i - e * (NWIN * NH);
        int w   = rem / NH;
        int h   = rem - w * NH;
        g_bias_t[(w * NH + h) * BIAS_E + e] = bt[i];
    }
}

// ====================== tf32 tensor-core GEMM (128x64 tile) ===================
#define KPAD 36

struct FragC { float c[2][4][4]; };  // [fm][fn][4]

__device__ __forceinline__ void gemm_tile_tf32(
    const float* __restrict__ X, const float* __restrict__ W,
    int bm, int bn, FragC& fc,
    float (*As)[KPAD], float (*Bs)[KPAD])
{
    const int t    = threadIdx.x;
    const int lane = t & 31;
    const int warp = t >> 5;
    const int wm   = warp & 3;
    const int wn   = warp >> 2;
    const int g    = lane >> 2;
    const int tg   = lane & 3;

    #pragma unroll
    for (int fm = 0; fm < 2; fm++)
        #pragma unroll
        for (int fn = 0; fn < 4; fn++)
            #pragma unroll
            for (int i = 0; i < 4; i++) fc.c[fm][fn][i] = 0.f;

    const int arow = t >> 1;
    const int acol = (t & 1) * 16;
    const int brow = t >> 2;
    const int bcol = (t & 3) * 8;

    const float* Xb = X + (size_t)(bm + arow) * NC + acol;
    const float* Wb = W + (size_t)(bn + brow) * NC + bcol;

    float4 pa[4], pb[2];
    #pragma unroll
    for (int i = 0; i < 4; i++) pa[i] = *(const float4*)(Xb + i * 4);
    #pragma unroll
    for (int i = 0; i < 2; i++) pb[i] = *(const float4*)(Wb + i * 4);

    for (int kc = 0; kc < NC; kc += 32) {
        #pragma unroll
        for (int i = 0; i < 4; i++) {
            uint32_t* d = (uint32_t*)&As[arow][acol + i * 4];
            d[0] = f2tf32(pa[i].x); d[1] = f2tf32(pa[i].y);
            d[2] = f2tf32(pa[i].z); d[3] = f2tf32(pa[i].w);
        }
        #pragma unroll
        for (int i = 0; i < 2; i++) {
            uint32_t* d = (uint32_t*)&Bs[brow][bcol + i * 4];
            d[0] = f2tf32(pb[i].x); d[1] = f2tf32(pb[i].y);
            d[2] = f2tf32(pb[i].z); d[3] = f2tf32(pb[i].w);
        }
        __syncthreads();

        if (kc + 32 < NC) {
            #pragma unroll
            for (int i = 0; i < 4; i++) pa[i] = *(const float4*)(Xb + kc + 32 + i * 4);
            #pragma unroll
            for (int i = 0; i < 2; i++) pb[i] = *(const float4*)(Wb + kc + 32 + i * 4);
        }

        #pragma unroll
        for (int kk = 0; kk < 4; kk++) {
            const int kb = kk * 8;
            uint32_t a[2][4], b[4][2];
            #pragma unroll
            for (int fm = 0; fm < 2; fm++) {
                const int r = wm * 32 + fm * 16 + g;
                const uint32_t* A0 = (const uint32_t*)As[r];
                const uint32_t* A8 = (const uint32_t*)As[r + 8];
                a[fm][0] = A0[kb + tg];
                a[fm][1] = A8[kb + tg];
                a[fm][2] = A0[kb + tg + 4];
                a[fm][3] = A8[kb + tg + 4];
            }
            #pragma unroll
            for (int fn = 0; fn < 4; fn++) {
                const uint32_t* B0 = (const uint32_t*)Bs[wn * 32 + fn * 8 + g];
                b[fn][0] = B0[kb + tg];
                b[fn][1] = B0[kb + tg + 4];
            }
            #pragma unroll
            for (int fm = 0; fm < 2; fm++)
                #pragma unroll
                for (int fn = 0; fn < 4; fn++)
                    mma_tf32(fc.c[fm][fn], a[fm][0], a[fm][1], a[fm][2], a[fm][3],
                             b[fn][0], b[fn][1]);
        }
        __syncthreads();
    }
}

// ---------------- QKV GEMM + scatter epilogue (q pre-scaled) -----------------
__global__ __launch_bounds__(256) void qkv_gemm_k(
    const float* __restrict__ X, const float* __restrict__ W,
    const float* __restrict__ bias)
{
    __shared__ float As[128][KPAD];
    __shared__ float Bs[64][KPAD];
    const int bm = blockIdx.y * 128;
    const int bn = blockIdx.x * 64;

    FragC fc;
    gemm_tile_tf32(X, W, bm, bn, fc, As, Bs);

    const int lane = threadIdx.x & 31;
    const int warp = threadIdx.x >> 5;
    const int wm = warp & 3, wn = warp >> 2;
    const int g = lane >> 2, tg = lane & 3;
    const float scale = 0.17677669529663687f;  // 1/sqrt(32)

    #pragma unroll
    for (int fm = 0; fm < 2; fm++) {
        #pragma unroll
        for (int i = 0; i < 2; i++) {
            const int row  = bm + wm * 32 + fm * 16 + g + i * 8;
            const int bidx = row / (NTOK * NWIN);
            const int rem  = row - bidx * (NTOK * NWIN);
            const int w    = rem / NTOK;
            const int n    = rem - w * NTOK;
            #pragma unroll
            for (int fn = 0; fn < 4; fn++) {
                const int col  = bn + wn * 32 + fn * 8 + 2 * tg;
                const int part = col / NC;
                const int c    = col - part * NC;
                const int h    = c >> 5, l = c & 31;
                float* buf = (part == 0) ? g_q : (part == 1) ? g_k : g_v;
                size_t dst = ((((size_t)(bidx * NH + h) * NWIN + w) * NTOK + n) << 5) + l;
                float2 v2 = make_float2(fc.c[fm][fn][2 * i]     + bias[col],
                                        fc.c[fm][fn][2 * i + 1] + bias[col + 1]);
                if (part == 0) { v2.x *= scale; v2.y *= scale; }
                *(float2*)(buf + dst) = v2;
            }
        }
    }
}

// ---------------- projection GEMM --------------------------------------------
__global__ __launch_bounds__(256) void proj_gemm_k(
    const float* __restrict__ W, const float* __restrict__ bias,
    float* __restrict__ out)
{
    __shared__ float As[128][KPAD];
    __shared__ float Bs[64][KPAD];
    const int bm = blockIdx.y * 128;
    const int bn = blockIdx.x * 64;

    FragC fc;
    gemm_tile_tf32(g_attn, W, bm, bn, fc, As, Bs);

    const int lane = threadIdx.x & 31;
    const int warp = threadIdx.x >> 5;
    const int wm = warp & 3, wn = warp >> 2;
    const int g = lane >> 2, tg = lane & 3;

    #pragma unroll
    for (int fm = 0; fm < 2; fm++) {
        #pragma unroll
        for (int i = 0; i < 2; i++) {
            const int row = bm + wm * 32 + fm * 16 + g + i * 8;
            #pragma unroll
            for (int fn = 0; fn < 4; fn++) {
                const int col = bn + wn * 32 + fn * 8 + 2 * tg;
                float2 v2 = make_float2(fc.c[fm][fn][2 * i]     + bias[col],
                                        fc.c[fm][fn][2 * i + 1] + bias[col + 1]);
                *(float2*)(out + (size_t)row * NC + col) = v2;
            }
        }
    }
}

// ================= tensor-core attention: CTA per (window, head) =============
// 9 warps; warp w owns query rows [16w, 16w+16). Full 144-col score rows per
// warp -> exact one-pass softmax in fragments. S=QK^T and O=PV via tf32 MMA.
// smem floats: sQ[144][36] | sK[144][36] | sVt[32][148] | sP[9][16][148] | moff
#define A_OFF_Q   0
#define A_OFF_K   5184
#define A_OFF_VT  10368
#define A_OFF_P   15104
#define A_OFF_MO  36416
#define A_SMEM_B  ((36416 + 144) * 4)   /* 146240 bytes */

__global__ __launch_bounds__(288) void attn_k(const float* __restrict__ mask) {
    extern __shared__ float sm[];
    float* sQ   = sm + A_OFF_Q;
    float* sK   = sm + A_OFF_K;
    float* sVt  = sm + A_OFF_VT;
    float* sP   = sm + A_OFF_P;
    int*   moff = (int*)(sm + A_OFF_MO);

    const int bx = blockIdx.x;          // bw * 6 + h
    const int h  = bx % NH;
    const int bw = bx / NH;
    const int b_ = bw >> 6;
    const int w  = bw & 63;
    const int t  = threadIdx.x;
    const int lane = t & 31, warp = t >> 5;
    const int g = lane >> 2, tg = lane & 3;

    const size_t off = (((size_t)(b_ * NH + h) * NWIN + w) * NTOK) << 5;

    // ---- load Q,K (row-major tf32, pad 36) and V transposed (pitch 148) ----
    {
        const float4* qg = (const float4*)(g_q + off);
        const float4* kg = (const float4*)(g_k + off);
        const float4* vg = (const float4*)(g_v + off);
        for (int i = t; i < NTOK * NL / 4; i += 288) {
            int row = i >> 3, c4 = (i & 7) * 4;
            float4 q4 = qg[i];
            uint32_t* dq = (uint32_t*)(sQ + row * 36 + c4);
            dq[0] = f2tf32(q4.x); dq[1] = f2tf32(q4.y);
            dq[2] = f2tf32(q4.z); dq[3] = f2tf32(q4.w);
            float4 k4 = kg[i];
            uint32_t* dk = (uint32_t*)(sK + row * 36 + c4);
            dk[0] = f2tf32(k4.x); dk[1] = f2tf32(k4.y);
            dk[2] = f2tf32(k4.z); dk[3] = f2tf32(k4.w);
            float4 v4 = vg[i];
            uint32_t* dv = (uint32_t*)sVt;
            dv[(c4 + 0) * 148 + row] = f2tf32(v4.x);
            dv[(c4 + 1) * 148 + row] = f2tf32(v4.y);
            dv[(c4 + 2) * 148 + row] = f2tf32(v4.z);
            dv[(c4 + 3) * 148 + row] = f2tf32(v4.w);
        }
    }
    if (t < NTOK) {
        int zm = t / 72, r = t - zm * 72, hm = r / 12, wm = r - hm * 12;
        moff[t] = 1656 * zm + 138 * hm - wm;
    }
    __syncthreads();

    const int r0 = warp * 16 + g;       // rows r0 (c0,c1) and r0+8 (c2,c3)

    // ---- S = Q @ K^T (18 n-tiles x 4 k-steps) ----
    float s[18][4];
    #pragma unroll
    for (int n = 0; n < 18; n++)
        #pragma unroll
        for (int i = 0; i < 4; i++) s[n][i] = 0.f;

    #pragma unroll
    for (int kk = 0; kk < 4; kk++) {
        const int kb = kk * 8;
        uint32_t a0 = *(const uint32_t*)(sQ + r0 * 36 + kb + tg);
        uint32_t a1 = *(const uint32_t*)(sQ + (r0 + 8) * 36 + kb + tg);
        uint32_t a2 = *(const uint32_t*)(sQ + r0 * 36 + kb + tg + 4);
        uint32_t a3 = *(const uint32_t*)(sQ + (r0 + 8) * 36 + kb + tg + 4);
        #pragma unroll
        for (int n = 0; n < 18; n++) {
            uint32_t b0 = *(const uint32_t*)(sK + (n * 8 + g) * 36 + kb + tg);
            uint32_t b1 = *(const uint32_t*)(sK + (n * 8 + g) * 36 + kb + tg + 4);
            mma_tf32(s[n], a0, a1, a2, a3, b0, b1);
        }
    }

    // ---- + bias + mask, row max ----
    const float* bt = g_bias_t + (size_t)(w * NH + h) * BIAS_E;
    int zn0 = r0 / 72, rn0 = r0 - zn0 * 72, hn0 = rn0 / 12, wn0 = rn0 - hn0 * 12;
    const int base0 = 828 * zn0 + 23 * hn0 + wn0 + 11;
    const int r1 = r0 + 8;
    int zn1 = r1 / 72, rn1 = r1 - zn1 * 72, hn1 = rn1 / 12, wn1 = rn1 - hn1 * 12;
    const int base1 = 828 * zn1 + 23 * hn1 + wn1 + 11;
    const float* m0 = mask + (size_t)bw * (NTOK * NTOK) + (size_t)r0 * NTOK;
    const float* m1 = m0 + 8 * NTOK;

    float mx0 = -1e30f, mx1 = -1e30f;
    #pragma unroll
    for (int n = 0; n < 18; n++) {
        const int c = n * 8 + 2 * tg;
        float2 mk0 = *(const float2*)(m0 + c);
        float2 mk1 = *(const float2*)(m1 + c);
        s[n][0] += __ldg(bt + base0 + moff[c])     + mk0.x;
        s[n][1] += __ldg(bt + base0 + moff[c + 1]) + mk0.y;
        s[n][2] += __ldg(bt + base1 + moff[c])     + mk1.x;
        s[n][3] += __ldg(bt + base1 + moff[c + 1]) + mk1.y;
        mx0 = fmaxf(mx0, fmaxf(s[n][0], s[n][1]));
        mx1 = fmaxf(mx1, fmaxf(s[n][2], s[n][3]));
    }
    mx0 = fmaxf(mx0, __shfl_xor_sync(0xffffffffu, mx0, 1));
    mx0 = fmaxf(mx0, __shfl_xor_sync(0xffffffffu, mx0, 2));
    mx1 = fmaxf(mx1, __shfl_xor_sync(0xffffffffu, mx1, 1));
    mx1 = fmaxf(mx1, __shfl_xor_sync(0xffffffffu, mx1, 2));

    // ---- exp, row sum, store P (tf32) to per-warp smem strip ----
    float sum0 = 0.f, sum1 = 0.f;
    float* p0 = sP + (size_t)r0 * 148;
    float* p1 = p0 + 8 * 148;
    #pragma unroll
    for (int n = 0; n < 18; n++) {
        const int c = n * 8 + 2 * tg;
        float e0 = __expf(s[n][0] - mx0), e1 = __expf(s[n][1] - mx0);
        float e2 = __expf(s[n][2] - mx1), e3 = __expf(s[n][3] - mx1);
        sum0 += e0 + e1;
        sum1 += e2 + e3;
        uint32_t* d0 = (uint32_t*)(p0 + c);
        d0[0] = f2tf32(e0); d0[1] = f2tf32(e1);
        uint32_t* d1 = (uint32_t*)(p1 + c);
        d1[0] = f2tf32(e2); d1[1] = f2tf32(e3);
    }
    sum0 += __shfl_xor_sync(0xffffffffu, sum0, 1);
    sum0 += __shfl_xor_sync(0xffffffffu, sum0, 2);
    sum1 += __shfl_xor_sync(0xffffffffu, sum1, 1);
    sum1 += __shfl_xor_sync(0xffffffffu, sum1, 2);
    __syncwarp();

    // ---- O = P @ V (4 n-tiles x 18 k-steps) ----
    float o[4][4];
    #pragma unroll
    for (int n = 0; n < 4; n++)
        #pragma unroll
        for (int i = 0; i < 4; i++) o[n][i] = 0.f;

    #pragma unroll
    for (int k = 0; k < 18; k++) {
        const int kb = k * 8;
        uint32_t a0 = *(const uint32_t*)(p0 + kb + tg);
        uint32_t a1 = *(const uint32_t*)(p1 + kb + tg);
        uint32_t a2 = *(const uint32_t*)(p0 + kb + tg + 4);
        uint32_t a3 = *(const uint32_t*)(p1 + kb + tg + 4);
        #pragma unroll
        for (int n = 0; n < 4; n++) {
            uint32_t b0 = *(const uint32_t*)(sVt + (n * 8 + g) * 148 + kb + tg);
            uint32_t b1 = *(const uint32_t*)(sVt + (n * 8 + g) * 148 + kb + tg + 4);
            mma_tf32(o[n], a0, a1, a2, a3, b0, b1);
        }
    }

    // ---- normalize and write out ----
    const float inv0 = 1.f / sum0, inv1 = 1.f / sum1;
    float* ob = g_attn + ((size_t)bw * NTOK) * NC + h * NL;
    #pragma unroll
    for (int n = 0; n < 4; n++) {
        const int c = n * 8 + 2 * tg;
        *(float2*)(ob + (size_t)r0 * NC + c) =
            make_float2(o[n][0] * inv0, o[n][1] * inv0);
        *(float2*)(ob + (size_t)(r0 + 8) * NC + c) =
            make_float2(o[n][2] * inv1, o[n][3] * inv1);
    }
}

// ---------------- launch --------------------------------------------------
extern "C" void kernel_launch(void* const* d_in, const int* in_sizes, int n_in,
                              void* d_out, int out_size)
{
    const float* x          = (const float*)d_in[0];
    const float* mask       = (const float*)d_in[1];
    const float* qkv_w      = (const float*)d_in[2];
    const float* qkv_b      = (const float*)d_in[3];
    const float* proj_w     = (const float*)d_in[4];
    const float* proj_b     = (const float*)d_in[5];
    const float* bias_table = (const float*)d_in[6];
    float* out = (float*)d_out;

    cudaFuncSetAttribute(attn_k, cudaFuncAttributeMaxDynamicSharedMemorySize,
                         A_SMEM_B);

    bias_transpose_k<<<(BIAS_E * NWIN * NH + 255) / 256, 256>>>(bias_table);
    qkv_gemm_k<<<dim3(9, MROWS / 128), 256>>>(x, qkv_w, qkv_b);
    attn_k<<<NB * NWIN * NH, 288, A_SMEM_B>>>(mask);
    proj_gemm_k<<<dim3(3, MROWS / 128), 256>>>(proj_w, proj_b, out);
}